// round 7
// baseline (speedup 1.0000x reference)
#include <cuda_runtime.h>
#include <cuda_bf16.h>
#include <cstdint>

// ExpandHarmonics. Output (float32): [hkl 3M | dHKL M | wav M | meta DM*M].
// R7: single-pass decoupled-lookback expand (count+scan+pack fused),
//     scatter with 1-pack-lookup/lane (DM>=16) + streaming stores.

#define MAXN   (1 << 20)
#define BLK    256
#define MAXB   ((MAXN + BLK - 1) / BLK)
#define MAXM   (1 << 23)

__device__ int                g_pack[MAXM];   // (src_idx << 8) | harmonic_n
__device__ unsigned int       g_hkl0[MAXN];   // h0 | k0<<8 | l0<<16
__device__ float              g_d0[MAXN];     // dHKL * g
__device__ float              g_w0[MAXN];     // wavelength * g
__device__ unsigned long long g_state[MAXB];  // lookback: status<<32 | value (memset 0 per launch)

__device__ __forceinline__ int gcd2(int a, int b) {
    while (b) { int t = a % b; a = b; b = t; }
    return a;
}

// ---- Pass 1: count + precompute + decoupled-lookback scan + pack, one kernel ----
__global__ __launch_bounds__(BLK)
void k_expand(const int* __restrict__ hkl, const float* __restrict__ dHKL,
              const float* __restrict__ wav, const float* __restrict__ dmin, int N) {
    const int b = blockIdx.x;
    const int t = threadIdx.x;
    const int wid = t >> 5, lane = t & 31;
    int i = b * BLK + t;

    int cnt = 0;
    if (i < N) {
        int h = hkl[3 * i], k = hkl[3 * i + 1], l = hkl[3 * i + 2];
        int g = gcd2(gcd2(h, k), l);
        float fg = (float)g;
        float d0 = dHKL[i] * fg;
        cnt = (int)floorf(d0 / dmin[0]);
        g_hkl0[i] = (unsigned)(h / g) | ((unsigned)(k / g) << 8) | ((unsigned)(l / g) << 16);
        g_d0[i] = d0;
        g_w0[i] = wav[i] * fg;
    }

    // warp inclusive scan
    int incl = cnt;
    #pragma unroll
    for (int o = 1; o < 32; o <<= 1) {
        int v = __shfl_up_sync(0xffffffffu, incl, o);
        if (lane >= o) incl += v;
    }
    __shared__ int s_wsum[8], s_wbase[8], s_total, s_exc;
    if (lane == 31) s_wsum[wid] = incl;
    __syncthreads();
    if (t == 0) {
        int run = 0;
        #pragma unroll
        for (int w = 0; w < 8; w++) { s_wbase[w] = run; run += s_wsum[w]; }
        s_total = run;
        // publish: block 0 -> prefix directly; else aggregate
        unsigned long long word = ((unsigned long long)(b == 0 ? 2 : 1) << 32) | (unsigned)run;
        *(volatile unsigned long long*)&g_state[b] = word;
        if (b == 0) s_exc = 0;
    }
    __syncthreads();

    // warp-parallel lookback (warp 0, b > 0)
    if (b > 0 && wid == 0) {
        unsigned exc = 0;
        int look = b - 1;
        while (true) {
            int j = look - lane;
            unsigned st; unsigned val;
            if (j >= 0) {
                unsigned long long w;
                do { w = *(volatile unsigned long long*)&g_state[j]; } while ((unsigned)(w >> 32) == 0u);
                st = (unsigned)(w >> 32); val = (unsigned)w;
            } else { st = 2u; val = 0u; }
            unsigned ball = __ballot_sync(0xffffffffu, st == 2u);
            if (ball) {
                int lp = __ffs(ball) - 1;            // nearest predecessor with a prefix
                unsigned contrib = (lane <= lp) ? val : 0u;
                exc += __reduce_add_sync(0xffffffffu, contrib);
                break;
            } else {
                exc += __reduce_add_sync(0xffffffffu, val);
                look -= 32;
            }
        }
        if (lane == 0) {
            s_exc = (int)exc;
            unsigned long long word = (2ull << 32) | (unsigned)(exc + (unsigned)s_total);
            *(volatile unsigned long long*)&g_state[b] = word;
        }
    }
    __syncthreads();

    if (i < N && cnt > 0) {
        int base = s_exc + s_wbase[wid] + (incl - cnt);
        int tag = i << 8;
        for (int n = 1; n <= cnt; n++)
            g_pack[base + n - 1] = tag | n;
    }
}

// ---- Pass 2 (fused): meta copy (blocks [0, metaBlocks)) + scalar outputs ----
// LEAD = (4-(5M)%4)%4 : out[5M+LEAD] is the first 16B-aligned slot.
// Warp chunk = 512 floats; lane j owns src floats [512w+16j, +16): 4 aligned
// float4 loads, composes 4 LEAD-shifted float4s, 4 aligned streaming stores.
template<int LEAD>
__global__ __launch_bounds__(256)
void k_fused(const float* __restrict__ meta, float* __restrict__ out,
             int M, int DMs, unsigned T, unsigned NV, int metaBlocks) {
    if ((int)blockIdx.x >= metaBlocks) {
        int m = (blockIdx.x - metaBlocks) * 256 + threadIdx.x;
        if (m < M) {
            int pack = g_pack[m];
            int idx = pack >> 8;
            int n   = pack & 255;
            unsigned hp = g_hkl0[idx];
            float fn = (float)n;
            __stcs(&out[3 * m + 0], (float)((int)(hp & 255u) * n));
            __stcs(&out[3 * m + 1], (float)((int)((hp >> 8) & 255u) * n));
            __stcs(&out[3 * m + 2], (float)((int)(hp >> 16) * n));
            __stcs(&out[3 * M + m], g_d0[idx] / fn);
            __stcs(&out[4 * M + m], g_w0[idx] / fn);
        }
        return;
    }

    const unsigned DMm = (1u << DMs) - 1u;
    const size_t gbase = (size_t)5 * M;

    unsigned w    = blockIdx.x * 8u + (threadIdx.x >> 5);
    int      lane = threadIdx.x & 31;
    unsigned base = w * 512u + (unsigned)lane * 16u;

    float a[20];
    if (DMs >= 4) {
        // lane's 16 floats lie in a single meta row: one pack lookup, contiguous 64B
        float4 v0, v1, v2, v3;
        v0 = v1 = v2 = v3 = make_float4(0.f, 0.f, 0.f, 0.f);
        if (base < T) {
            unsigned idx = ((unsigned)__ldg(&g_pack[base >> DMs])) >> 8;
            const float4* src = (const float4*)(meta + (size_t)((idx << DMs) + (base & DMm)));
            v0 = src[0]; v1 = src[1]; v2 = src[2]; v3 = src[3];
        }
        a[0]=v0.x; a[1]=v0.y; a[2]=v0.z; a[3]=v0.w;
        a[4]=v1.x; a[5]=v1.y; a[6]=v1.z; a[7]=v1.w;
        a[8]=v2.x; a[9]=v2.y; a[10]=v2.z; a[11]=v2.w;
        a[12]=v3.x; a[13]=v3.y; a[14]=v3.z; a[15]=v3.w;
    } else {
        #pragma unroll
        for (int u = 0; u < 4; u++) {
            unsigned p = base + 4u * u;
            float4 v = make_float4(0.f, 0.f, 0.f, 0.f);
            if (p < T) {
                unsigned idx = ((unsigned)__ldg(&g_pack[p >> DMs])) >> 8;
                v = *(const float4*)(meta + (size_t)((idx << DMs) + (p & DMm)));
            }
            a[4*u+0]=v.x; a[4*u+1]=v.y; a[4*u+2]=v.z; a[4*u+3]=v.w;
        }
    }

    if (LEAD != 0) {
        float4 nx = make_float4(0.f, 0.f, 0.f, 0.f);
        if (lane == 31) {
            unsigned p2 = w * 512u + 512u;
            if (p2 < T) {
                unsigned idx = ((unsigned)__ldg(&g_pack[p2 >> DMs])) >> 8;
                nx = *(const float4*)(meta + (size_t)((idx << DMs) + (p2 & DMm)));
            }
        }
        float s0 = __shfl_down_sync(0xffffffffu, a[0], 1);
        float s1 = __shfl_down_sync(0xffffffffu, a[1], 1);
        float s2 = __shfl_down_sync(0xffffffffu, a[2], 1);
        float s3 = __shfl_down_sync(0xffffffffu, a[3], 1);
        a[16] = (lane == 31) ? nx.x : s0;
        a[17] = (lane == 31) ? nx.y : s1;
        a[18] = (lane == 31) ? nx.z : s2;
        a[19] = (lane == 31) ? nx.w : s3;
    }

    unsigned f0 = w * 128u + (unsigned)lane * 4u;
    float* dstf = out + gbase + (size_t)LEAD;
    #pragma unroll
    for (int k2 = 0; k2 < 4; k2++) {
        unsigned f = f0 + (unsigned)k2;
        if (f < NV) {
            float4 o = make_float4(a[LEAD + 4*k2 + 0], a[LEAD + 4*k2 + 1],
                                   a[LEAD + 4*k2 + 2], a[LEAD + 4*k2 + 3]);
            __stcs((float4*)(dstf + 4 * (size_t)f), o);
        }
    }

    if (blockIdx.x == 0 && threadIdx.x < 32) {
        if (lane < LEAD) {
            unsigned idx = ((unsigned)g_pack[0]) >> 8;
            out[gbase + lane] = meta[(size_t)((idx << DMs) + lane)];
        }
        unsigned done = (unsigned)LEAD + 4u * NV;
        unsigned tail = T - done;
        if (lane >= 4 && lane < 4 + (int)tail) {
            unsigned p = done + (unsigned)(lane - 4);
            unsigned idx = ((unsigned)g_pack[p >> DMs]) >> 8;
            out[gbase + p] = meta[(size_t)((idx << DMs) + (p & DMm))];
        }
    }
}

// ---- Fallbacks (DM not power of two) ----
__global__ __launch_bounds__(256)
void k_scalar_fb(float* __restrict__ out, int M) {
    int m = blockIdx.x * 256 + threadIdx.x;
    if (m >= M) return;
    int pack = g_pack[m];
    int idx = pack >> 8;
    int n   = pack & 255;
    unsigned hp = g_hkl0[idx];
    float fn = (float)n;
    out[3 * m + 0] = (float)((int)(hp & 255u) * n);
    out[3 * m + 1] = (float)((int)((hp >> 8) & 255u) * n);
    out[3 * m + 2] = (float)((int)(hp >> 16) * n);
    out[3 * M + m] = g_d0[idx] / fn;
    out[4 * M + m] = g_w0[idx] / fn;
}

__global__ __launch_bounds__(256)
void k_meta_fb(const float* __restrict__ meta, float* __restrict__ out, int M, int DM) {
    int gw   = (blockIdx.x * 256 + threadIdx.x) >> 5;
    int lane = threadIdx.x & 31;
    int r = lane >> 3;
    int c = lane & 7;
    int m = gw * 4 + r;
    if (m >= M) return;
    int idx = g_pack[m] >> 8;
    const float* src = meta + (size_t)idx * DM;
    float*       dst = out + (size_t)5 * M + (size_t)m * DM;
    for (int e = c; e < DM; e += 8)
        dst[e] = src[e];
}

extern "C" void kernel_launch(void* const* d_in, const int* in_sizes, int n_in,
                              void* d_out, int out_size) {
    const int*   hkl  = (const int*)  d_in[0];
    const float* dHKL = (const float*)d_in[1];
    const float* wav  = (const float*)d_in[2];
    const float* meta = (const float*)d_in[3];
    const float* dmin = (const float*)d_in[4];

    int N  = in_sizes[1];
    int DM = in_sizes[3] / N;
    int M  = out_size / (5 + DM);

    int B = (N + BLK - 1) / BLK;

    // reset lookback state (captured as a memset node; not an allocation)
    void* statePtr = nullptr;
    cudaGetSymbolAddress(&statePtr, g_state);
    cudaMemsetAsync(statePtr, 0, (size_t)B * sizeof(unsigned long long), 0);

    k_expand<<<B, BLK>>>(hkl, dHKL, wav, dmin, N);

    bool pow2 = (DM >= 4) && ((DM & (DM - 1)) == 0);
    if (pow2) {
        int DMs = 0; while ((1 << DMs) < DM) DMs++;
        unsigned T = (unsigned)((size_t)M << DMs);
        int lead = (int)((4u - ((5u * (unsigned)M) & 3u)) & 3u);
        unsigned NV = (T - (unsigned)lead) >> 2;
        unsigned metaWarps = (NV + 127u) / 128u;
        int metaBlocks = (int)((metaWarps + 7u) / 8u);
        int scalarBlocks = (M + 255) / 256;
        int grid = metaBlocks + scalarBlocks;
        switch (lead) {
            case 0: k_fused<0><<<grid, 256>>>(meta, (float*)d_out, M, DMs, T, NV, metaBlocks); break;
            case 1: k_fused<1><<<grid, 256>>>(meta, (float*)d_out, M, DMs, T, NV, metaBlocks); break;
            case 2: k_fused<2><<<grid, 256>>>(meta, (float*)d_out, M, DMs, T, NV, metaBlocks); break;
            default: k_fused<3><<<grid, 256>>>(meta, (float*)d_out, M, DMs, T, NV, metaBlocks); break;
        }
    } else {
        k_scalar_fb<<<(M + 255) / 256, 256>>>((float*)d_out, M);
        int rowsPerBlock = 8 * 4;
        k_meta_fb<<<(M + rowsPerBlock - 1) / rowsPerBlock, 256>>>(meta, (float*)d_out, M, DM);
    }
}

// round 8
// speedup vs baseline: 1.2298x; 1.2298x over previous
#include <cuda_runtime.h>
#include <cuda_bf16.h>
#include <cstdint>

// ExpandHarmonics. Output (float32): [hkl 3M | dHKL M | wav M | meta DM*M].
// R8: lane-consecutive float4 mapping (dense 512B L1 wavefronts on LDG+STG),
//     LEAD shift via per-step shuffles; R6 3-kernel expand (lookback reverted).

#define MAXN   (1 << 20)
#define BLK    256
#define MAXB   ((MAXN + BLK - 1) / BLK)
#define MAXM   (1 << 23)

__device__ int           g_rowoff[MAXN];
__device__ unsigned char g_cnt[MAXN];
__device__ int           g_blocksum[MAXB + 1];
__device__ int           g_pack[MAXM];       // (src_idx << 8) | harmonic_n
__device__ unsigned int  g_hkl0[MAXN];       // h0 | k0<<8 | l0<<16
__device__ float         g_d0[MAXN];         // dHKL * g
__device__ float         g_w0[MAXN];         // wavelength * g

__device__ __forceinline__ int gcd2(int a, int b) {
    while (b) { int t = a % b; a = b; b = t; }
    return a;
}

// ---- Pass 1: per-row count + precompute + in-block scan ----
__global__ __launch_bounds__(BLK)
void k_count(const int* __restrict__ hkl, const float* __restrict__ dHKL,
             const float* __restrict__ wav, const float* __restrict__ dmin, int N) {
    __shared__ int s[BLK];
    int i = blockIdx.x * BLK + threadIdx.x;
    int cnt = 0;
    if (i < N) {
        int h = hkl[3 * i], k = hkl[3 * i + 1], l = hkl[3 * i + 2];
        int g = gcd2(gcd2(h, k), l);
        float fg = (float)g;
        float d0 = dHKL[i] * fg;
        cnt = (int)floorf(d0 / dmin[0]);
        g_hkl0[i] = (unsigned)(h / g) | ((unsigned)(k / g) << 8) | ((unsigned)(l / g) << 16);
        g_d0[i] = d0;
        g_w0[i] = wav[i] * fg;
    }
    s[threadIdx.x] = cnt;
    __syncthreads();
    #pragma unroll
    for (int off = 1; off < BLK; off <<= 1) {
        int t = (threadIdx.x >= off) ? s[threadIdx.x - off] : 0;
        __syncthreads();
        s[threadIdx.x] += t;
        __syncthreads();
    }
    if (i < N) {
        g_rowoff[i] = s[threadIdx.x] - cnt;
        g_cnt[i]    = (unsigned char)cnt;
    }
    if (threadIdx.x == 0) g_blocksum[blockIdx.x] = s[BLK - 1];
}

// ---- Pass 2: single-block exclusive scan of block sums ----
__global__ __launch_bounds__(1024)
void k_scan_blocks(int B) {
    __shared__ int s[1024];
    int tid = threadIdx.x;
    int ipt = (B + 1023) / 1024;
    int local[8];
    int start = tid * ipt;
    int sum = 0;
    for (int j = 0; j < ipt; j++) {
        int idx = start + j;
        int v = (idx < B) ? g_blocksum[idx] : 0;
        local[j] = sum;
        sum += v;
    }
    s[tid] = sum;
    __syncthreads();
    #pragma unroll
    for (int off = 1; off < 1024; off <<= 1) {
        int t = (tid >= off) ? s[tid - off] : 0;
        __syncthreads();
        s[tid] += t;
        __syncthreads();
    }
    int base = s[tid] - sum;
    for (int j = 0; j < ipt; j++) {
        int idx = start + j;
        if (idx < B) g_blocksum[idx] = base + local[j];
    }
    if (tid == 1023) g_blocksum[B] = s[1023];
}

// ---- Pass 3: per-output-row (idx, n) pack ----
__global__ __launch_bounds__(BLK)
void k_pack(int N) {
    int i = blockIdx.x * BLK + threadIdx.x;
    if (i >= N) return;
    int off = g_rowoff[i] + g_blocksum[blockIdx.x];
    int cnt = g_cnt[i];
    int tag = i << 8;
    for (int n = 1; n <= cnt; n++)
        g_pack[off + n - 1] = tag | n;
}

// ---- Pass 4 (fused): meta copy (blocks [0, metaBlocks)) + scalar outputs ----
// Output vector group f covers out floats [5M+LEAD+4f, +4) = src floats [LEAD+4f, +4).
// Lane j handles groups fb = w*128 + j + 32*k2 -> consecutive lanes own consecutive
// 16B chunks: every LDG.128 / STG.128 is a dense 512B wavefront.
// Source group g = src floats [4g, +4): always inside one meta row (DM % 4 == 0).
// LEAD-shift: o(f) = combine(v(f), v(f+1)); v(f+1) via shfl_down, lane31 takes
// lane0's group of step k2+1 (k2=3: boundary group w*128+128, loaded by lane 0).
template<int LEAD>
__global__ __launch_bounds__(256)
void k_fused(const float* __restrict__ meta, float* __restrict__ out,
             int M, int DMs, unsigned T, unsigned NV, int metaBlocks) {
    if ((int)blockIdx.x >= metaBlocks) {
        int m = (blockIdx.x - metaBlocks) * 256 + threadIdx.x;
        if (m < M) {
            int pack = g_pack[m];
            int idx = pack >> 8;
            int n   = pack & 255;
            unsigned hp = g_hkl0[idx];
            float fn = (float)n;
            out[3 * m + 0] = (float)((int)(hp & 255u) * n);
            out[3 * m + 1] = (float)((int)((hp >> 8) & 255u) * n);
            out[3 * m + 2] = (float)((int)(hp >> 16) * n);
            out[3 * M + m] = g_d0[idx] / fn;
            out[4 * M + m] = g_w0[idx] / fn;
        }
        return;
    }

    const unsigned DMm = (1u << DMs) - 1u;
    const size_t gbase = (size_t)5 * M;
    const unsigned GMAX = T >> 2;                 // total source groups (T%4==0)

    unsigned w    = blockIdx.x * 8u + (threadIdx.x >> 5);
    int      lane = threadIdx.x & 31;
    unsigned fb   = w * 128u + (unsigned)lane;    // lane's first group

    float4 v[5];
    #pragma unroll
    for (int k2 = 0; k2 < 4; k2++) {
        unsigned g = fb + 32u * (unsigned)k2;
        v[k2] = make_float4(0.f, 0.f, 0.f, 0.f);
        if (g < GMAX) {
            unsigned p = 4u * g;
            unsigned idx = ((unsigned)__ldg(&g_pack[p >> DMs])) >> 8;
            v[k2] = *(const float4*)(meta + (size_t)((idx << DMs) + (p & DMm)));
        }
    }
    if (LEAD != 0) {
        v[4] = make_float4(0.f, 0.f, 0.f, 0.f);
        if (lane == 0) {
            unsigned g = w * 128u + 128u;        // next warp-chunk's first group
            if (g < GMAX) {
                unsigned p = 4u * g;
                unsigned idx = ((unsigned)__ldg(&g_pack[p >> DMs])) >> 8;
                v[4] = *(const float4*)(meta + (size_t)((idx << DMs) + (p & DMm)));
            }
        }
    }

    float* dstf = out + gbase + (size_t)LEAD;
    #pragma unroll
    for (int k2 = 0; k2 < 4; k2++) {
        float4 o;
        if (LEAD == 0) {
            o = v[k2];
        } else {
            float4 vnext = (k2 < 3) ? v[k2 + 1] : v[4];
            float nx = __shfl_sync(0xffffffffu, vnext.x, 0);
            float sx = __shfl_down_sync(0xffffffffu, v[k2].x, 1);
            float vnx = (lane == 31) ? nx : sx;
            float vny = 0.f, vnz = 0.f;
            if (LEAD >= 2) {
                float ny = __shfl_sync(0xffffffffu, vnext.y, 0);
                float sy = __shfl_down_sync(0xffffffffu, v[k2].y, 1);
                vny = (lane == 31) ? ny : sy;
            }
            if (LEAD == 3) {
                float nz = __shfl_sync(0xffffffffu, vnext.z, 0);
                float sz = __shfl_down_sync(0xffffffffu, v[k2].z, 1);
                vnz = (lane == 31) ? nz : sz;
            }
            if (LEAD == 1)      o = make_float4(v[k2].y, v[k2].z, v[k2].w, vnx);
            else if (LEAD == 2) o = make_float4(v[k2].z, v[k2].w, vnx, vny);
            else                o = make_float4(v[k2].w, vnx, vny, vnz);
        }
        unsigned f = fb + 32u * (unsigned)k2;
        if (f < NV)
            *(float4*)(dstf + 4 * (size_t)f) = o;
    }

    // head + tail scalars
    if (blockIdx.x == 0 && threadIdx.x < 32) {
        if (lane < LEAD) {
            unsigned idx = ((unsigned)g_pack[0]) >> 8;
            out[gbase + lane] = meta[(size_t)((idx << DMs) + lane)];
        }
        unsigned done = (unsigned)LEAD + 4u * NV;
        unsigned tail = T - done;                 // 0..3
        if (lane >= 4 && lane < 4 + (int)tail) {
            unsigned p = done + (unsigned)(lane - 4);
            unsigned idx = ((unsigned)g_pack[p >> DMs]) >> 8;
            out[gbase + p] = meta[(size_t)((idx << DMs) + (p & DMm))];
        }
    }
}

// ---- Fallbacks (DM not power of two) ----
__global__ __launch_bounds__(256)
void k_scalar_fb(float* __restrict__ out, int M) {
    int m = blockIdx.x * 256 + threadIdx.x;
    if (m >= M) return;
    int pack = g_pack[m];
    int idx = pack >> 8;
    int n   = pack & 255;
    unsigned hp = g_hkl0[idx];
    float fn = (float)n;
    out[3 * m + 0] = (float)((int)(hp & 255u) * n);
    out[3 * m + 1] = (float)((int)((hp >> 8) & 255u) * n);
    out[3 * m + 2] = (float)((int)(hp >> 16) * n);
    out[3 * M + m] = g_d0[idx] / fn;
    out[4 * M + m] = g_w0[idx] / fn;
}

__global__ __launch_bounds__(256)
void k_meta_fb(const float* __restrict__ meta, float* __restrict__ out, int M, int DM) {
    int gw   = (blockIdx.x * 256 + threadIdx.x) >> 5;
    int lane = threadIdx.x & 31;
    int r = lane >> 3;
    int c = lane & 7;
    int m = gw * 4 + r;
    if (m >= M) return;
    int idx = g_pack[m] >> 8;
    const float* src = meta + (size_t)idx * DM;
    float*       dst = out + (size_t)5 * M + (size_t)m * DM;
    for (int e = c; e < DM; e += 8)
        dst[e] = src[e];
}

extern "C" void kernel_launch(void* const* d_in, const int* in_sizes, int n_in,
                              void* d_out, int out_size) {
    const int*   hkl  = (const int*)  d_in[0];
    const float* dHKL = (const float*)d_in[1];
    const float* wav  = (const float*)d_in[2];
    const float* meta = (const float*)d_in[3];
    const float* dmin = (const float*)d_in[4];

    int N  = in_sizes[1];
    int DM = in_sizes[3] / N;
    int M  = out_size / (5 + DM);

    int B = (N + BLK - 1) / BLK;

    k_count<<<B, BLK>>>(hkl, dHKL, wav, dmin, N);
    k_scan_blocks<<<1, 1024>>>(B);
    k_pack<<<B, BLK>>>(N);

    bool pow2 = (DM >= 4) && ((DM & (DM - 1)) == 0);
    if (pow2) {
        int DMs = 0; while ((1 << DMs) < DM) DMs++;
        unsigned T = (unsigned)((size_t)M << DMs);
        int lead = (int)((4u - ((5u * (unsigned)M) & 3u)) & 3u);
        unsigned NV = (T - (unsigned)lead) >> 2;
        unsigned metaWarps = (NV + 127u) / 128u;
        int metaBlocks = (int)((metaWarps + 7u) / 8u);
        int scalarBlocks = (M + 255) / 256;
        int grid = metaBlocks + scalarBlocks;
        switch (lead) {
            case 0: k_fused<0><<<grid, 256>>>(meta, (float*)d_out, M, DMs, T, NV, metaBlocks); break;
            case 1: k_fused<1><<<grid, 256>>>(meta, (float*)d_out, M, DMs, T, NV, metaBlocks); break;
            case 2: k_fused<2><<<grid, 256>>>(meta, (float*)d_out, M, DMs, T, NV, metaBlocks); break;
            default: k_fused<3><<<grid, 256>>>(meta, (float*)d_out, M, DMs, T, NV, metaBlocks); break;
        }
    } else {
        k_scalar_fb<<<(M + 255) / 256, 256>>>((float*)d_out, M);
        int rowsPerBlock = 8 * 4;
        k_meta_fb<<<(M + rowsPerBlock - 1) / rowsPerBlock, 256>>>(meta, (float*)d_out, M, DM);
    }
}

// round 9
// speedup vs baseline: 1.2446x; 1.0120x over previous
#include <cuda_runtime.h>
#include <cuda_bf16.h>
#include <cstdint>

// ExpandHarmonics. Output (float32): [hkl 3M | dHKL M | wav M | meta DM*M].
// R9: 2-kernel expand (warp-shuffle scan in count; pack computes its own
//     block prefix from L2-resident block sums) + R8 lane-consecutive copy.

#define MAXN   (1 << 20)
#define BLK    256
#define MAXB   ((MAXN + BLK - 1) / BLK)
#define MAXM   (1 << 23)

__device__ int           g_rowoff[MAXN];     // per-row exclusive offset within block
__device__ unsigned char g_cnt[MAXN];
__device__ int           g_blocksum[MAXB];   // per-block totals (NOT scanned)
__device__ int           g_pack[MAXM];       // (src_idx << 8) | harmonic_n
__device__ unsigned int  g_hkl0[MAXN];       // h0 | k0<<8 | l0<<16
__device__ float         g_d0[MAXN];         // dHKL * g
__device__ float         g_w0[MAXN];         // wavelength * g

__device__ __forceinline__ int gcd2(int a, int b) {
    while (b) { int t = a % b; a = b; b = t; }
    return a;
}

// ---- Pass 1: per-row count + precompute + warp-shuffle block scan ----
__global__ __launch_bounds__(BLK)
void k_count(const int* __restrict__ hkl, const float* __restrict__ dHKL,
             const float* __restrict__ wav, const float* __restrict__ dmin, int N) {
    const int t = threadIdx.x;
    const int wid = t >> 5, lane = t & 31;
    int i = blockIdx.x * BLK + t;

    int cnt = 0;
    if (i < N) {
        int h = hkl[3 * i], k = hkl[3 * i + 1], l = hkl[3 * i + 2];
        int g = gcd2(gcd2(h, k), l);
        float fg = (float)g;
        float d0 = dHKL[i] * fg;
        cnt = (int)floorf(d0 / dmin[0]);
        g_hkl0[i] = (unsigned)(h / g) | ((unsigned)(k / g) << 8) | ((unsigned)(l / g) << 16);
        g_d0[i] = d0;
        g_w0[i] = wav[i] * fg;
    }

    // warp inclusive scan
    int incl = cnt;
    #pragma unroll
    for (int o = 1; o < 32; o <<= 1) {
        int v = __shfl_up_sync(0xffffffffu, incl, o);
        if (lane >= o) incl += v;
    }
    __shared__ int s_wbase[8];
    if (lane == 31) s_wbase[wid] = incl;
    __syncthreads();
    if (wid == 0) {
        int v = (lane < 8) ? s_wbase[lane] : 0;
        int sc = v;
        #pragma unroll
        for (int o = 1; o < 8; o <<= 1) {
            int u = __shfl_up_sync(0xffffffffu, sc, o);
            if (lane >= o) sc += u;
        }
        if (lane < 8) s_wbase[lane] = sc - v;          // exclusive warp bases
        if (lane == 7) g_blocksum[blockIdx.x] = sc;    // block total
    }
    __syncthreads();

    if (i < N) {
        g_rowoff[i] = s_wbase[wid] + (incl - cnt);
        g_cnt[i]    = (unsigned char)cnt;
    }
}

// ---- Pass 2: pack; each block derives its global base by summing prior block sums ----
__global__ __launch_bounds__(BLK)
void k_pack(int N) {
    const int b = blockIdx.x;
    const int t = threadIdx.x;
    const int wid = t >> 5, lane = t & 31;

    // sum g_blocksum[0..b) across the block (values are L2-resident, ~16 loads/thread)
    int partial = 0;
    for (int j = t; j < b; j += BLK) partial += g_blocksum[j];
    #pragma unroll
    for (int o = 16; o > 0; o >>= 1)
        partial += __shfl_down_sync(0xffffffffu, partial, o);
    __shared__ int s_w[8];
    __shared__ int s_base;
    if (lane == 0) s_w[wid] = partial;
    __syncthreads();
    if (t == 0) {
        int s = 0;
        #pragma unroll
        for (int w = 0; w < 8; w++) s += s_w[w];
        s_base = s;
    }
    __syncthreads();

    int i = b * BLK + t;
    if (i >= N) return;
    int off = s_base + g_rowoff[i];
    int cnt = g_cnt[i];
    int tag = i << 8;
    for (int n = 1; n <= cnt; n++)
        g_pack[off + n - 1] = tag | n;
}

// ---- Pass 3 (fused): meta copy (blocks [0, metaBlocks)) + scalar outputs ----
// Output vector group f covers out floats [5M+LEAD+4f, +4) = src floats [LEAD+4f, +4).
// Lane j handles groups fb = w*128 + j + 32*k2 -> dense 512B L1 wavefronts.
template<int LEAD>
__global__ __launch_bounds__(256)
void k_fused(const float* __restrict__ meta, float* __restrict__ out,
             int M, int DMs, unsigned T, unsigned NV, int metaBlocks) {
    if ((int)blockIdx.x >= metaBlocks) {
        int m = (blockIdx.x - metaBlocks) * 256 + threadIdx.x;
        if (m < M) {
            int pack = g_pack[m];
            int idx = pack >> 8;
            int n   = pack & 255;
            unsigned hp = g_hkl0[idx];
            float fn = (float)n;
            out[3 * m + 0] = (float)((int)(hp & 255u) * n);
            out[3 * m + 1] = (float)((int)((hp >> 8) & 255u) * n);
            out[3 * m + 2] = (float)((int)(hp >> 16) * n);
            out[3 * M + m] = g_d0[idx] / fn;
            out[4 * M + m] = g_w0[idx] / fn;
        }
        return;
    }

    const unsigned DMm = (1u << DMs) - 1u;
    const size_t gbase = (size_t)5 * M;
    const unsigned GMAX = T >> 2;

    unsigned w    = blockIdx.x * 8u + (threadIdx.x >> 5);
    int      lane = threadIdx.x & 31;
    unsigned fb   = w * 128u + (unsigned)lane;

    float4 v[5];
    #pragma unroll
    for (int k2 = 0; k2 < 4; k2++) {
        unsigned g = fb + 32u * (unsigned)k2;
        v[k2] = make_float4(0.f, 0.f, 0.f, 0.f);
        if (g < GMAX) {
            unsigned p = 4u * g;
            unsigned idx = ((unsigned)__ldg(&g_pack[p >> DMs])) >> 8;
            v[k2] = *(const float4*)(meta + (size_t)((idx << DMs) + (p & DMm)));
        }
    }
    if (LEAD != 0) {
        v[4] = make_float4(0.f, 0.f, 0.f, 0.f);
        if (lane == 0) {
            unsigned g = w * 128u + 128u;
            if (g < GMAX) {
                unsigned p = 4u * g;
                unsigned idx = ((unsigned)__ldg(&g_pack[p >> DMs])) >> 8;
                v[4] = *(const float4*)(meta + (size_t)((idx << DMs) + (p & DMm)));
            }
        }
    }

    float* dstf = out + gbase + (size_t)LEAD;
    #pragma unroll
    for (int k2 = 0; k2 < 4; k2++) {
        float4 o;
        if (LEAD == 0) {
            o = v[k2];
        } else {
            float4 vnext = (k2 < 3) ? v[k2 + 1] : v[4];
            float nx = __shfl_sync(0xffffffffu, vnext.x, 0);
            float sx = __shfl_down_sync(0xffffffffu, v[k2].x, 1);
            float vnx = (lane == 31) ? nx : sx;
            float vny = 0.f, vnz = 0.f;
            if (LEAD >= 2) {
                float ny = __shfl_sync(0xffffffffu, vnext.y, 0);
                float sy = __shfl_down_sync(0xffffffffu, v[k2].y, 1);
                vny = (lane == 31) ? ny : sy;
            }
            if (LEAD == 3) {
                float nz = __shfl_sync(0xffffffffu, vnext.z, 0);
                float sz = __shfl_down_sync(0xffffffffu, v[k2].z, 1);
                vnz = (lane == 31) ? nz : sz;
            }
            if (LEAD == 1)      o = make_float4(v[k2].y, v[k2].z, v[k2].w, vnx);
            else if (LEAD == 2) o = make_float4(v[k2].z, v[k2].w, vnx, vny);
            else                o = make_float4(v[k2].w, vnx, vny, vnz);
        }
        unsigned f = fb + 32u * (unsigned)k2;
        if (f < NV)
            *(float4*)(dstf + 4 * (size_t)f) = o;
    }

    if (blockIdx.x == 0 && threadIdx.x < 32) {
        if (lane < LEAD) {
            unsigned idx = ((unsigned)g_pack[0]) >> 8;
            out[gbase + lane] = meta[(size_t)((idx << DMs) + lane)];
        }
        unsigned done = (unsigned)LEAD + 4u * NV;
        unsigned tail = T - done;
        if (lane >= 4 && lane < 4 + (int)tail) {
            unsigned p = done + (unsigned)(lane - 4);
            unsigned idx = ((unsigned)g_pack[p >> DMs]) >> 8;
            out[gbase + p] = meta[(size_t)((idx << DMs) + (p & DMm))];
        }
    }
}

// ---- Fallbacks (DM not power of two) ----
__global__ __launch_bounds__(256)
void k_scalar_fb(float* __restrict__ out, int M) {
    int m = blockIdx.x * 256 + threadIdx.x;
    if (m >= M) return;
    int pack = g_pack[m];
    int idx = pack >> 8;
    int n   = pack & 255;
    unsigned hp = g_hkl0[idx];
    float fn = (float)n;
    out[3 * m + 0] = (float)((int)(hp & 255u) * n);
    out[3 * m + 1] = (float)((int)((hp >> 8) & 255u) * n);
    out[3 * m + 2] = (float)((int)(hp >> 16) * n);
    out[3 * M + m] = g_d0[idx] / fn;
    out[4 * M + m] = g_w0[idx] / fn;
}

__global__ __launch_bounds__(256)
void k_meta_fb(const float* __restrict__ meta, float* __restrict__ out, int M, int DM) {
    int gw   = (blockIdx.x * 256 + threadIdx.x) >> 5;
    int lane = threadIdx.x & 31;
    int r = lane >> 3;
    int c = lane & 7;
    int m = gw * 4 + r;
    if (m >= M) return;
    int idx = g_pack[m] >> 8;
    const float* src = meta + (size_t)idx * DM;
    float*       dst = out + (size_t)5 * M + (size_t)m * DM;
    for (int e = c; e < DM; e += 8)
        dst[e] = src[e];
}

extern "C" void kernel_launch(void* const* d_in, const int* in_sizes, int n_in,
                              void* d_out, int out_size) {
    const int*   hkl  = (const int*)  d_in[0];
    const float* dHKL = (const float*)d_in[1];
    const float* wav  = (const float*)d_in[2];
    const float* meta = (const float*)d_in[3];
    const float* dmin = (const float*)d_in[4];

    int N  = in_sizes[1];
    int DM = in_sizes[3] / N;
    int M  = out_size / (5 + DM);

    int B = (N + BLK - 1) / BLK;

    k_count<<<B, BLK>>>(hkl, dHKL, wav, dmin, N);
    k_pack<<<B, BLK>>>(N);

    bool pow2 = (DM >= 4) && ((DM & (DM - 1)) == 0);
    if (pow2) {
        int DMs = 0; while ((1 << DMs) < DM) DMs++;
        unsigned T = (unsigned)((size_t)M << DMs);
        int lead = (int)((4u - ((5u * (unsigned)M) & 3u)) & 3u);
        unsigned NV = (T - (unsigned)lead) >> 2;
        unsigned metaWarps = (NV + 127u) / 128u;
        int metaBlocks = (int)((metaWarps + 7u) / 8u);
        int scalarBlocks = (M + 255) / 256;
        int grid = metaBlocks + scalarBlocks;
        switch (lead) {
            case 0: k_fused<0><<<grid, 256>>>(meta, (float*)d_out, M, DMs, T, NV, metaBlocks); break;
            case 1: k_fused<1><<<grid, 256>>>(meta, (float*)d_out, M, DMs, T, NV, metaBlocks); break;
            case 2: k_fused<2><<<grid, 256>>>(meta, (float*)d_out, M, DMs, T, NV, metaBlocks); break;
            default: k_fused<3><<<grid, 256>>>(meta, (float*)d_out, M, DMs, T, NV, metaBlocks); break;
        }
    } else {
        k_scalar_fb<<<(M + 255) / 256, 256>>>((float*)d_out, M);
        int rowsPerBlock = 8 * 4;
        k_meta_fb<<<(M + rowsPerBlock - 1) / rowsPerBlock, 256>>>(meta, (float*)d_out, M, DM);
    }
}

// round 10
// speedup vs baseline: 1.2970x; 1.0421x over previous
#include <cuda_runtime.h>
#include <cuda_bf16.h>
#include <cstdint>

// ExpandHarmonics. Output (float32): [hkl 3M | dHKL M | wav M | meta DM*M].
// R10: binary gcd + reciprocal-multiply exact division in k_count;
//      R9 2-kernel expand + R8 lane-consecutive fused copy.

#define MAXN   (1 << 20)
#define BLK    256
#define MAXB   ((MAXN + BLK - 1) / BLK)
#define MAXM   (1 << 23)

__device__ int           g_rowoff[MAXN];     // per-row exclusive offset within block
__device__ unsigned char g_cnt[MAXN];
__device__ int           g_blocksum[MAXB];   // per-block totals (NOT scanned)
__device__ int           g_pack[MAXM];       // (src_idx << 8) | harmonic_n
__device__ unsigned int  g_hkl0[MAXN];       // h0 | k0<<8 | l0<<16
__device__ float         g_d0[MAXN];         // dHKL * g
__device__ float         g_w0[MAXN];         // wavelength * g

// binary gcd, a,b >= 1 (no integer division)
__device__ __forceinline__ int bgcd(int a, int b) {
    int s = __ffs(a | b) - 1;
    a >>= (__ffs(a) - 1);
    do {
        b >>= (__ffs(b) - 1);
        if (a > b) { int t = a; a = b; b = t; }
        b -= a;
    } while (b);
    return a << s;
}

// ---- Pass 1: per-row count + precompute + warp-shuffle block scan ----
__global__ __launch_bounds__(BLK)
void k_count(const int* __restrict__ hkl, const float* __restrict__ dHKL,
             const float* __restrict__ wav, const float* __restrict__ dmin, int N) {
    const int t = threadIdx.x;
    const int wid = t >> 5, lane = t & 31;
    int i = blockIdx.x * BLK + t;

    int cnt = 0;
    if (i < N) {
        int h = hkl[3 * i], k = hkl[3 * i + 1], l = hkl[3 * i + 2];
        int g = bgcd(bgcd(h, k), l);
        float fg = (float)g;
        float rg = 1.0f / fg;                     // exact-integer quotients via rn
        float d0 = dHKL[i] * fg;
        cnt = (int)floorf(d0 / __ldg(dmin));
        unsigned h0 = (unsigned)__float2int_rn((float)h * rg);
        unsigned k0 = (unsigned)__float2int_rn((float)k * rg);
        unsigned l0 = (unsigned)__float2int_rn((float)l * rg);
        g_hkl0[i] = h0 | (k0 << 8) | (l0 << 16);
        g_d0[i] = d0;
        g_w0[i] = wav[i] * fg;
    }

    // warp inclusive scan
    int incl = cnt;
    #pragma unroll
    for (int o = 1; o < 32; o <<= 1) {
        int v = __shfl_up_sync(0xffffffffu, incl, o);
        if (lane >= o) incl += v;
    }
    __shared__ int s_wbase[8];
    if (lane == 31) s_wbase[wid] = incl;
    __syncthreads();
    if (wid == 0) {
        int v = (lane < 8) ? s_wbase[lane] : 0;
        int sc = v;
        #pragma unroll
        for (int o = 1; o < 8; o <<= 1) {
            int u = __shfl_up_sync(0xffffffffu, sc, o);
            if (lane >= o) sc += u;
        }
        if (lane < 8) s_wbase[lane] = sc - v;
        if (lane == 7) g_blocksum[blockIdx.x] = sc;
    }
    __syncthreads();

    if (i < N) {
        g_rowoff[i] = s_wbase[wid] + (incl - cnt);
        g_cnt[i]    = (unsigned char)cnt;
    }
}

// ---- Pass 2: pack; each block derives its global base from prior block sums ----
__global__ __launch_bounds__(BLK)
void k_pack(int N) {
    const int b = blockIdx.x;
    const int t = threadIdx.x;
    const int wid = t >> 5, lane = t & 31;

    int partial = 0;
    for (int j = t; j < b; j += BLK) partial += g_blocksum[j];
    #pragma unroll
    for (int o = 16; o > 0; o >>= 1)
        partial += __shfl_down_sync(0xffffffffu, partial, o);
    __shared__ int s_w[8];
    __shared__ int s_base;
    if (lane == 0) s_w[wid] = partial;
    __syncthreads();
    if (t == 0) {
        int s = 0;
        #pragma unroll
        for (int w = 0; w < 8; w++) s += s_w[w];
        s_base = s;
    }
    __syncthreads();

    int i = b * BLK + t;
    if (i >= N) return;
    int off = s_base + g_rowoff[i];
    int cnt = g_cnt[i];
    int tag = i << 8;
    for (int n = 1; n <= cnt; n++)
        g_pack[off + n - 1] = tag | n;
}

// ---- Pass 3 (fused): meta copy (blocks [0, metaBlocks)) + scalar outputs ----
// Lane j handles output groups fb = w*128 + j + 32*k2 -> dense 512B L1 wavefronts.
template<int LEAD>
__global__ __launch_bounds__(256)
void k_fused(const float* __restrict__ meta, float* __restrict__ out,
             int M, int DMs, unsigned T, unsigned NV, int metaBlocks) {
    if ((int)blockIdx.x >= metaBlocks) {
        int m = (blockIdx.x - metaBlocks) * 256 + threadIdx.x;
        if (m < M) {
            int pack = g_pack[m];
            int idx = pack >> 8;
            int n   = pack & 255;
            unsigned hp = g_hkl0[idx];
            float fn = (float)n;
            out[3 * m + 0] = (float)((int)(hp & 255u) * n);
            out[3 * m + 1] = (float)((int)((hp >> 8) & 255u) * n);
            out[3 * m + 2] = (float)((int)(hp >> 16) * n);
            out[3 * M + m] = g_d0[idx] / fn;
            out[4 * M + m] = g_w0[idx] / fn;
        }
        return;
    }

    const unsigned DMm = (1u << DMs) - 1u;
    const size_t gbase = (size_t)5 * M;
    const unsigned GMAX = T >> 2;

    unsigned w    = blockIdx.x * 8u + (threadIdx.x >> 5);
    int      lane = threadIdx.x & 31;
    unsigned fb   = w * 128u + (unsigned)lane;

    float4 v[5];
    #pragma unroll
    for (int k2 = 0; k2 < 4; k2++) {
        unsigned g = fb + 32u * (unsigned)k2;
        v[k2] = make_float4(0.f, 0.f, 0.f, 0.f);
        if (g < GMAX) {
            unsigned p = 4u * g;
            unsigned idx = ((unsigned)__ldg(&g_pack[p >> DMs])) >> 8;
            v[k2] = *(const float4*)(meta + (size_t)((idx << DMs) + (p & DMm)));
        }
    }
    if (LEAD != 0) {
        v[4] = make_float4(0.f, 0.f, 0.f, 0.f);
        if (lane == 0) {
            unsigned g = w * 128u + 128u;
            if (g < GMAX) {
                unsigned p = 4u * g;
                unsigned idx = ((unsigned)__ldg(&g_pack[p >> DMs])) >> 8;
                v[4] = *(const float4*)(meta + (size_t)((idx << DMs) + (p & DMm)));
            }
        }
    }

    float* dstf = out + gbase + (size_t)LEAD;
    #pragma unroll
    for (int k2 = 0; k2 < 4; k2++) {
        float4 o;
        if (LEAD == 0) {
            o = v[k2];
        } else {
            float4 vnext = (k2 < 3) ? v[k2 + 1] : v[4];
            float nx = __shfl_sync(0xffffffffu, vnext.x, 0);
            float sx = __shfl_down_sync(0xffffffffu, v[k2].x, 1);
            float vnx = (lane == 31) ? nx : sx;
            float vny = 0.f, vnz = 0.f;
            if (LEAD >= 2) {
                float ny = __shfl_sync(0xffffffffu, vnext.y, 0);
                float sy = __shfl_down_sync(0xffffffffu, v[k2].y, 1);
                vny = (lane == 31) ? ny : sy;
            }
            if (LEAD == 3) {
                float nz = __shfl_sync(0xffffffffu, vnext.z, 0);
                float sz = __shfl_down_sync(0xffffffffu, v[k2].z, 1);
                vnz = (lane == 31) ? nz : sz;
            }
            if (LEAD == 1)      o = make_float4(v[k2].y, v[k2].z, v[k2].w, vnx);
            else if (LEAD == 2) o = make_float4(v[k2].z, v[k2].w, vnx, vny);
            else                o = make_float4(v[k2].w, vnx, vny, vnz);
        }
        unsigned f = fb + 32u * (unsigned)k2;
        if (f < NV)
            *(float4*)(dstf + 4 * (size_t)f) = o;
    }

    if (blockIdx.x == 0 && threadIdx.x < 32) {
        if (lane < LEAD) {
            unsigned idx = ((unsigned)g_pack[0]) >> 8;
            out[gbase + lane] = meta[(size_t)((idx << DMs) + lane)];
        }
        unsigned done = (unsigned)LEAD + 4u * NV;
        unsigned tail = T - done;
        if (lane >= 4 && lane < 4 + (int)tail) {
            unsigned p = done + (unsigned)(lane - 4);
            unsigned idx = ((unsigned)g_pack[p >> DMs]) >> 8;
            out[gbase + p] = meta[(size_t)((idx << DMs) + (p & DMm))];
        }
    }
}

// ---- Fallbacks (DM not power of two) ----
__global__ __launch_bounds__(256)
void k_scalar_fb(float* __restrict__ out, int M) {
    int m = blockIdx.x * 256 + threadIdx.x;
    if (m >= M) return;
    int pack = g_pack[m];
    int idx = pack >> 8;
    int n   = pack & 255;
    unsigned hp = g_hkl0[idx];
    float fn = (float)n;
    out[3 * m + 0] = (float)((int)(hp & 255u) * n);
    out[3 * m + 1] = (float)((int)((hp >> 8) & 255u) * n);
    out[3 * m + 2] = (float)((int)(hp >> 16) * n);
    out[3 * M + m] = g_d0[idx] / fn;
    out[4 * M + m] = g_w0[idx] / fn;
}

__global__ __launch_bounds__(256)
void k_meta_fb(const float* __restrict__ meta, float* __restrict__ out, int M, int DM) {
    int gw   = (blockIdx.x * 256 + threadIdx.x) >> 5;
    int lane = threadIdx.x & 31;
    int r = lane >> 3;
    int c = lane & 7;
    int m = gw * 4 + r;
    if (m >= M) return;
    int idx = g_pack[m] >> 8;
    const float* src = meta + (size_t)idx * DM;
    float*       dst = out + (size_t)5 * M + (size_t)m * DM;
    for (int e = c; e < DM; e += 8)
        dst[e] = src[e];
}

extern "C" void kernel_launch(void* const* d_in, const int* in_sizes, int n_in,
                              void* d_out, int out_size) {
    const int*   hkl  = (const int*)  d_in[0];
    const float* dHKL = (const float*)d_in[1];
    const float* wav  = (const float*)d_in[2];
    const float* meta = (const float*)d_in[3];
    const float* dmin = (const float*)d_in[4];

    int N  = in_sizes[1];
    int DM = in_sizes[3] / N;
    int M  = out_size / (5 + DM);

    int B = (N + BLK - 1) / BLK;

    k_count<<<B, BLK>>>(hkl, dHKL, wav, dmin, N);
    k_pack<<<B, BLK>>>(N);

    bool pow2 = (DM >= 4) && ((DM & (DM - 1)) == 0);
    if (pow2) {
        int DMs = 0; while ((1 << DMs) < DM) DMs++;
        unsigned T = (unsigned)((size_t)M << DMs);
        int lead = (int)((4u - ((5u * (unsigned)M) & 3u)) & 3u);
        unsigned NV = (T - (unsigned)lead) >> 2;
        unsigned metaWarps = (NV + 127u) / 128u;
        int metaBlocks = (int)((metaWarps + 7u) / 8u);
        int scalarBlocks = (M + 255) / 256;
        int grid = metaBlocks + scalarBlocks;
        switch (lead) {
            case 0: k_fused<0><<<grid, 256>>>(meta, (float*)d_out, M, DMs, T, NV, metaBlocks); break;
            case 1: k_fused<1><<<grid, 256>>>(meta, (float*)d_out, M, DMs, T, NV, metaBlocks); break;
            case 2: k_fused<2><<<grid, 256>>>(meta, (float*)d_out, M, DMs, T, NV, metaBlocks); break;
            default: k_fused<3><<<grid, 256>>>(meta, (float*)d_out, M, DMs, T, NV, metaBlocks); break;
        }
    } else {
        k_scalar_fb<<<(M + 255) / 256, 256>>>((float*)d_out, M);
        int rowsPerBlock = 8 * 4;
        k_meta_fb<<<(M + rowsPerBlock - 1) / rowsPerBlock, 256>>>(meta, (float*)d_out, M, DM);
    }
}

// round 11
// speedup vs baseline: 1.3025x; 1.0043x over previous
#include <cuda_runtime.h>
#include <cuda_bf16.h>
#include <cstdint>

// ExpandHarmonics. Output (float32): [hkl 3M | dHKL M | wav M | meta DM*M].
// R11: 4-rows-per-thread vectorized count/pack passes; R8/R10 fused copy kernel.

#define MAXN   (1 << 20)
#define BLK    256
#define ROWS_PT 4
#define ROWS_PB (BLK * ROWS_PT)                  // 1024 rows per block
#define MAXB   ((MAXN + ROWS_PB - 1) / ROWS_PB)
#define MAXM   (1 << 23)

__device__ int           g_rowoff[MAXN];     // per-row exclusive offset within block
__device__ unsigned char g_cnt[MAXN];
__device__ int           g_blocksum[MAXB];   // per-block totals (NOT scanned)
__device__ int           g_pack[MAXM];       // (src_idx << 8) | harmonic_n
__device__ unsigned int  g_hkl0[MAXN];       // h0 | k0<<8 | l0<<16
__device__ float         g_d0[MAXN];         // dHKL * g
__device__ float         g_w0[MAXN];         // wavelength * g

// binary gcd, a,b >= 1 (no integer division)
__device__ __forceinline__ int bgcd(int a, int b) {
    int s = __ffs(a | b) - 1;
    a >>= (__ffs(a) - 1);
    do {
        b >>= (__ffs(b) - 1);
        if (a > b) { int t = a; a = b; b = t; }
        b -= a;
    } while (b);
    return a << s;
}

// ---- Pass 1: count + precompute, 4 rows/thread, vector LDG/STG ----
__global__ __launch_bounds__(BLK)
void k_count(const int* __restrict__ hkl, const float* __restrict__ dHKL,
             const float* __restrict__ wav, const float* __restrict__ dmin, int N) {
    const int t = threadIdx.x;
    const int wid = t >> 5, lane = t & 31;
    const int i0 = blockIdx.x * ROWS_PB + t * ROWS_PT;
    const float dm = __ldg(dmin);

    int hh[4], kk[4], ll[4];
    float dv[4], wv[4];
    bool full = (i0 + ROWS_PT <= N);
    if (full) {
        const int4* hp = (const int4*)(hkl + 3 * i0);    // 3*i0 % 4 == 0
        int4 a = hp[0], b = hp[1], c = hp[2];
        hh[0]=a.x; kk[0]=a.y; ll[0]=a.z;
        hh[1]=a.w; kk[1]=b.x; ll[1]=b.y;
        hh[2]=b.z; kk[2]=b.w; ll[2]=c.x;
        hh[3]=c.y; kk[3]=c.z; ll[3]=c.w;
        float4 d4 = *(const float4*)(dHKL + i0);
        float4 w4 = *(const float4*)(wav + i0);
        dv[0]=d4.x; dv[1]=d4.y; dv[2]=d4.z; dv[3]=d4.w;
        wv[0]=w4.x; wv[1]=w4.y; wv[2]=w4.z; wv[3]=w4.w;
    } else {
        #pragma unroll
        for (int j = 0; j < 4; j++) {
            int i = i0 + j;
            if (i < N) {
                hh[j]=hkl[3*i]; kk[j]=hkl[3*i+1]; ll[j]=hkl[3*i+2];
                dv[j]=dHKL[i]; wv[j]=wav[i];
            } else { hh[j]=1; kk[j]=1; ll[j]=1; dv[j]=0.f; wv[j]=0.f; }
        }
    }

    int cnt[4];
    unsigned hk0[4];
    float d0v[4], w0v[4];
    #pragma unroll
    for (int j = 0; j < 4; j++) {
        int g = bgcd(bgcd(hh[j], kk[j]), ll[j]);
        float fg = (float)g;
        float rg = 1.0f / fg;
        float d0 = dv[j] * fg;
        int c = (int)floorf(d0 / dm);
        bool valid = (i0 + j < N);
        cnt[j] = valid ? c : 0;
        unsigned h0 = (unsigned)__float2int_rn((float)hh[j] * rg);
        unsigned k0 = (unsigned)__float2int_rn((float)kk[j] * rg);
        unsigned l0 = (unsigned)__float2int_rn((float)ll[j] * rg);
        hk0[j] = h0 | (k0 << 8) | (l0 << 16);
        d0v[j] = d0;
        w0v[j] = wv[j] * fg;
    }
    int tsum = cnt[0] + cnt[1] + cnt[2] + cnt[3];

    // warp inclusive scan over thread sums
    int incl = tsum;
    #pragma unroll
    for (int o = 1; o < 32; o <<= 1) {
        int v = __shfl_up_sync(0xffffffffu, incl, o);
        if (lane >= o) incl += v;
    }
    __shared__ int s_wbase[8];
    if (lane == 31) s_wbase[wid] = incl;
    __syncthreads();
    if (wid == 0) {
        int v = (lane < 8) ? s_wbase[lane] : 0;
        int sc = v;
        #pragma unroll
        for (int o = 1; o < 8; o <<= 1) {
            int u = __shfl_up_sync(0xffffffffu, sc, o);
            if (lane >= o) sc += u;
        }
        if (lane < 8) s_wbase[lane] = sc - v;
        if (lane == 7) g_blocksum[blockIdx.x] = sc;
    }
    __syncthreads();

    int texc = s_wbase[wid] + (incl - tsum);     // thread's exclusive offset in block
    int ro[4];
    ro[0] = texc;
    ro[1] = ro[0] + cnt[0];
    ro[2] = ro[1] + cnt[1];
    ro[3] = ro[2] + cnt[2];

    if (full) {
        *(uint4*)(g_hkl0 + i0)  = make_uint4(hk0[0], hk0[1], hk0[2], hk0[3]);
        *(float4*)(g_d0 + i0)   = make_float4(d0v[0], d0v[1], d0v[2], d0v[3]);
        *(float4*)(g_w0 + i0)   = make_float4(w0v[0], w0v[1], w0v[2], w0v[3]);
        *(int4*)(g_rowoff + i0) = make_int4(ro[0], ro[1], ro[2], ro[3]);
        uchar4 c4 = make_uchar4((unsigned char)cnt[0], (unsigned char)cnt[1],
                                (unsigned char)cnt[2], (unsigned char)cnt[3]);
        *(uchar4*)(g_cnt + i0) = c4;
    } else {
        #pragma unroll
        for (int j = 0; j < 4; j++) {
            int i = i0 + j;
            if (i < N) {
                g_hkl0[i] = hk0[j]; g_d0[i] = d0v[j]; g_w0[i] = w0v[j];
                g_rowoff[i] = ro[j]; g_cnt[i] = (unsigned char)cnt[j];
            }
        }
    }
}

// ---- Pass 2: pack; block derives its global base from prior block sums ----
__global__ __launch_bounds__(BLK)
void k_pack(int N) {
    const int b = blockIdx.x;
    const int t = threadIdx.x;
    const int wid = t >> 5, lane = t & 31;

    int partial = 0;
    for (int j = t; j < b; j += BLK) partial += g_blocksum[j];
    #pragma unroll
    for (int o = 16; o > 0; o >>= 1)
        partial += __shfl_down_sync(0xffffffffu, partial, o);
    __shared__ int s_w[8];
    __shared__ int s_base;
    if (lane == 0) s_w[wid] = partial;
    __syncthreads();
    if (t == 0) {
        int s = 0;
        #pragma unroll
        for (int w = 0; w < 8; w++) s += s_w[w];
        s_base = s;
    }
    __syncthreads();

    int i0 = b * ROWS_PB + t * ROWS_PT;
    if (i0 >= N) return;
    if (i0 + ROWS_PT <= N) {
        int4 ro = *(const int4*)(g_rowoff + i0);
        uchar4 c4 = *(const uchar4*)(g_cnt + i0);
        int roa[4] = {ro.x, ro.y, ro.z, ro.w};
        int ca[4]  = {c4.x, c4.y, c4.z, c4.w};
        #pragma unroll
        for (int j = 0; j < 4; j++) {
            int off = s_base + roa[j];
            int tag = (i0 + j) << 8;
            for (int n = 1; n <= ca[j]; n++)
                g_pack[off + n - 1] = tag | n;
        }
    } else {
        for (int j = 0; j < 4; j++) {
            int i = i0 + j;
            if (i >= N) break;
            int off = s_base + g_rowoff[i];
            int cnt = g_cnt[i];
            int tag = i << 8;
            for (int n = 1; n <= cnt; n++)
                g_pack[off + n - 1] = tag | n;
        }
    }
}

// ---- Pass 3 (fused): meta copy (blocks [0, metaBlocks)) + scalar outputs ----
template<int LEAD>
__global__ __launch_bounds__(256)
void k_fused(const float* __restrict__ meta, float* __restrict__ out,
             int M, int DMs, unsigned T, unsigned NV, int metaBlocks) {
    if ((int)blockIdx.x >= metaBlocks) {
        int m = (blockIdx.x - metaBlocks) * 256 + threadIdx.x;
        if (m < M) {
            int pack = g_pack[m];
            int idx = pack >> 8;
            int n   = pack & 255;
            unsigned hp = g_hkl0[idx];
            float fn = (float)n;
            out[3 * m + 0] = (float)((int)(hp & 255u) * n);
            out[3 * m + 1] = (float)((int)((hp >> 8) & 255u) * n);
            out[3 * m + 2] = (float)((int)(hp >> 16) * n);
            out[3 * M + m] = g_d0[idx] / fn;
            out[4 * M + m] = g_w0[idx] / fn;
        }
        return;
    }

    const unsigned DMm = (1u << DMs) - 1u;
    const size_t gbase = (size_t)5 * M;
    const unsigned GMAX = T >> 2;

    unsigned w    = blockIdx.x * 8u + (threadIdx.x >> 5);
    int      lane = threadIdx.x & 31;
    unsigned fb   = w * 128u + (unsigned)lane;

    float4 v[5];
    #pragma unroll
    for (int k2 = 0; k2 < 4; k2++) {
        unsigned g = fb + 32u * (unsigned)k2;
        v[k2] = make_float4(0.f, 0.f, 0.f, 0.f);
        if (g < GMAX) {
            unsigned p = 4u * g;
            unsigned idx = ((unsigned)__ldg(&g_pack[p >> DMs])) >> 8;
            v[k2] = *(const float4*)(meta + (size_t)((idx << DMs) + (p & DMm)));
        }
    }
    if (LEAD != 0) {
        v[4] = make_float4(0.f, 0.f, 0.f, 0.f);
        if (lane == 0) {
            unsigned g = w * 128u + 128u;
            if (g < GMAX) {
                unsigned p = 4u * g;
                unsigned idx = ((unsigned)__ldg(&g_pack[p >> DMs])) >> 8;
                v[4] = *(const float4*)(meta + (size_t)((idx << DMs) + (p & DMm)));
            }
        }
    }

    float* dstf = out + gbase + (size_t)LEAD;
    #pragma unroll
    for (int k2 = 0; k2 < 4; k2++) {
        float4 o;
        if (LEAD == 0) {
            o = v[k2];
        } else {
            float4 vnext = (k2 < 3) ? v[k2 + 1] : v[4];
            float nx = __shfl_sync(0xffffffffu, vnext.x, 0);
            float sx = __shfl_down_sync(0xffffffffu, v[k2].x, 1);
            float vnx = (lane == 31) ? nx : sx;
            float vny = 0.f, vnz = 0.f;
            if (LEAD >= 2) {
                float ny = __shfl_sync(0xffffffffu, vnext.y, 0);
                float sy = __shfl_down_sync(0xffffffffu, v[k2].y, 1);
                vny = (lane == 31) ? ny : sy;
            }
            if (LEAD == 3) {
                float nz = __shfl_sync(0xffffffffu, vnext.z, 0);
                float sz = __shfl_down_sync(0xffffffffu, v[k2].z, 1);
                vnz = (lane == 31) ? nz : sz;
            }
            if (LEAD == 1)      o = make_float4(v[k2].y, v[k2].z, v[k2].w, vnx);
            else if (LEAD == 2) o = make_float4(v[k2].z, v[k2].w, vnx, vny);
            else                o = make_float4(v[k2].w, vnx, vny, vnz);
        }
        unsigned f = fb + 32u * (unsigned)k2;
        if (f < NV)
            *(float4*)(dstf + 4 * (size_t)f) = o;
    }

    if (blockIdx.x == 0 && threadIdx.x < 32) {
        if (lane < LEAD) {
            unsigned idx = ((unsigned)g_pack[0]) >> 8;
            out[gbase + lane] = meta[(size_t)((idx << DMs) + lane)];
        }
        unsigned done = (unsigned)LEAD + 4u * NV;
        unsigned tail = T - done;
        if (lane >= 4 && lane < 4 + (int)tail) {
            unsigned p = done + (unsigned)(lane - 4);
            unsigned idx = ((unsigned)g_pack[p >> DMs]) >> 8;
            out[gbase + p] = meta[(size_t)((idx << DMs) + (p & DMm))];
        }
    }
}

// ---- Fallbacks (DM not power of two) ----
__global__ __launch_bounds__(256)
void k_scalar_fb(float* __restrict__ out, int M) {
    int m = blockIdx.x * 256 + threadIdx.x;
    if (m >= M) return;
    int pack = g_pack[m];
    int idx = pack >> 8;
    int n   = pack & 255;
    unsigned hp = g_hkl0[idx];
    float fn = (float)n;
    out[3 * m + 0] = (float)((int)(hp & 255u) * n);
    out[3 * m + 1] = (float)((int)((hp >> 8) & 255u) * n);
    out[3 * m + 2] = (float)((int)(hp >> 16) * n);
    out[3 * M + m] = g_d0[idx] / fn;
    out[4 * M + m] = g_w0[idx] / fn;
}

__global__ __launch_bounds__(256)
void k_meta_fb(const float* __restrict__ meta, float* __restrict__ out, int M, int DM) {
    int gw   = (blockIdx.x * 256 + threadIdx.x) >> 5;
    int lane = threadIdx.x & 31;
    int r = lane >> 3;
    int c = lane & 7;
    int m = gw * 4 + r;
    if (m >= M) return;
    int idx = g_pack[m] >> 8;
    const float* src = meta + (size_t)idx * DM;
    float*       dst = out + (size_t)5 * M + (size_t)m * DM;
    for (int e = c; e < DM; e += 8)
        dst[e] = src[e];
}

extern "C" void kernel_launch(void* const* d_in, const int* in_sizes, int n_in,
                              void* d_out, int out_size) {
    const int*   hkl  = (const int*)  d_in[0];
    const float* dHKL = (const float*)d_in[1];
    const float* wav  = (const float*)d_in[2];
    const float* meta = (const float*)d_in[3];
    const float* dmin = (const float*)d_in[4];

    int N  = in_sizes[1];
    int DM = in_sizes[3] / N;
    int M  = out_size / (5 + DM);

    int B = (N + ROWS_PB - 1) / ROWS_PB;

    k_count<<<B, BLK>>>(hkl, dHKL, wav, dmin, N);
    k_pack<<<B, BLK>>>(N);

    bool pow2 = (DM >= 4) && ((DM & (DM - 1)) == 0);
    if (pow2) {
        int DMs = 0; while ((1 << DMs) < DM) DMs++;
        unsigned T = (unsigned)((size_t)M << DMs);
        int lead = (int)((4u - ((5u * (unsigned)M) & 3u)) & 3u);
        unsigned NV = (T - (unsigned)lead) >> 2;
        unsigned metaWarps = (NV + 127u) / 128u;
        int metaBlocks = (int)((metaWarps + 7u) / 8u);
        int scalarBlocks = (M + 255) / 256;
        int grid = metaBlocks + scalarBlocks;
        switch (lead) {
            case 0: k_fused<0><<<grid, 256>>>(meta, (float*)d_out, M, DMs, T, NV, metaBlocks); break;
            case 1: k_fused<1><<<grid, 256>>>(meta, (float*)d_out, M, DMs, T, NV, metaBlocks); break;
            case 2: k_fused<2><<<grid, 256>>>(meta, (float*)d_out, M, DMs, T, NV, metaBlocks); break;
            default: k_fused<3><<<grid, 256>>>(meta, (float*)d_out, M, DMs, T, NV, metaBlocks); break;
        }
    } else {
        k_scalar_fb<<<(M + 255) / 256, 256>>>((float*)d_out, M);
        int rowsPerBlock = 8 * 4;
        k_meta_fb<<<(M + rowsPerBlock - 1) / rowsPerBlock, 256>>>(meta, (float*)d_out, M, DM);
    }
}